// round 10
// baseline (speedup 1.0000x reference)
#include <cuda_runtime.h>
#include <cuda_fp16.h>
#include <cstdint>
#include <math.h>

// ---------------------------------------------------------------------------
// Problem constants
// ---------------------------------------------------------------------------
#define NB   2
#define S    2048
#define DM   1024
#define NH   16
#define HD   64
#define DFF  4096
#define TOK  (NB * S)
#define LN_EPS 1e-5f

// ---------------------------------------------------------------------------
// Scratch (static device globals; no runtime allocation allowed)
// ---------------------------------------------------------------------------
__device__ __half g_xnh [(size_t)TOK * DM];
__device__ __half g_qkv [(size_t)TOK * 3 * DM];   // packed Q|K|V, ld = 3072
__device__ __half g_aoh [(size_t)TOK * DM];
__device__ __half g_ffh [(size_t)TOK * DFF];
__device__ float  g_x2  [(size_t)TOK * DM];
__device__ __half g_wqkvt[(size_t)3 * DM * DM];   // [3072][1024] K-major
__device__ __half g_w0t [(size_t)DM * DM];
__device__ __half g_w1t [(size_t)DFF * DM];
__device__ __half g_w2t [(size_t)DM * DFF];

// ---------------------------------------------------------------------------
// Helpers
// ---------------------------------------------------------------------------
__device__ __forceinline__ void mma_f16(float* c, const uint32_t* a,
                                        uint32_t b0, uint32_t b1) {
    asm volatile(
        "mma.sync.aligned.m16n8k16.row.col.f32.f16.f16.f32 "
        "{%0,%1,%2,%3}, {%4,%5,%6,%7}, {%8,%9}, {%0,%1,%2,%3};"
        : "+f"(c[0]), "+f"(c[1]), "+f"(c[2]), "+f"(c[3])
        : "r"(a[0]), "r"(a[1]), "r"(a[2]), "r"(a[3]), "r"(b0), "r"(b1));
}
__device__ __forceinline__ uint32_t packh2(float x, float y) {
    __half2 h = __floats2half2_rn(x, y);
    return *(uint32_t*)&h;
}
__device__ __forceinline__ void cpa16(uint32_t dst, const void* src) {
    asm volatile("cp.async.cg.shared.global [%0], [%1], 16;" :: "r"(dst), "l"(src));
}
__device__ __forceinline__ void cpa_commit() {
    asm volatile("cp.async.commit_group;" ::: "memory");
}
__device__ __forceinline__ void cpa_wait1() {
    asm volatile("cp.async.wait_group 1;" ::: "memory");
}
__device__ __forceinline__ void ldm4(uint32_t& r0, uint32_t& r1, uint32_t& r2,
                                     uint32_t& r3, uint32_t addr) {
    asm volatile("ldmatrix.sync.aligned.m8n8.x4.shared.b16 {%0,%1,%2,%3}, [%4];"
                 : "=r"(r0), "=r"(r1), "=r"(r2), "=r"(r3) : "r"(addr));
}

// ---------------------------------------------------------------------------
// hgemm256: 256x128 CTA tile, 8 warps (4M x 2N), warp tile 64x64.
// fp16 in (A [M][K], B [N][K] K-major), fp16 out, optional bias/relu.
// cp.async 3-stage pipeline, ldmatrix fragments, SK=40 padding.
// ---------------------------------------------------------------------------
template<bool BIAS, bool RELU>
__global__ __launch_bounds__(256) void hgemm256(
    const __half* __restrict__ A, int lda,
    const __half* __restrict__ B, int ldb,
    __half* __restrict__ C, int ldc,
    const float* __restrict__ bias, int K)
{
    constexpr int BM = 256, BN = 128, BK = 32, SK = 40, STG = 3;
    constexpr int A_H = BM * SK, B_H = BN * SK;          // halves per stage
    extern __shared__ char smem_raw[];
    __half* As = (__half*)smem_raw;                      // [STG][BM][SK]
    __half* Bs = (__half*)(smem_raw + STG * A_H * 2);    // [STG][BN][SK]

    const int tid = threadIdx.x;
    const int wid = tid >> 5, lane = tid & 31;
    const int warpM = wid & 3, warpN = wid >> 2;
    const int g = lane >> 2, q4 = lane & 3;

    const __half* Ab = A + (size_t)blockIdx.y * BM * lda;
    const __half* Bb = B + (size_t)blockIdx.x * BN * ldb;

    const int r0c = tid >> 2, c0 = (tid & 3) * 8;
    const uint32_t as_u32 = (uint32_t)__cvta_generic_to_shared(As);
    const uint32_t bs_u32 = (uint32_t)__cvta_generic_to_shared(Bs);
    const uint32_t dstA = as_u32 + (uint32_t)(r0c * SK + c0) * 2;
    const uint32_t dstB = bs_u32 + (uint32_t)(r0c * SK + c0) * 2;

    const int gsel = lane >> 3, rin = lane & 7;
    const uint32_t offA = (uint32_t)(((warpM * 64 + (gsel & 1) * 8 + rin) * SK
                                      + (gsel >> 1) * 8) * 2);
    const uint32_t offB = (uint32_t)(((warpN * 64 + (gsel >> 1) * 8 + rin) * SK
                                      + (gsel & 1) * 8) * 2);

    float acc[4][8][4];
    #pragma unroll
    for (int mt = 0; mt < 4; mt++)
        #pragma unroll
        for (int nt = 0; nt < 8; nt++)
            #pragma unroll
            for (int j = 0; j < 4; j++) acc[mt][nt][j] = 0.0f;

    const int nit = K / BK;

    #pragma unroll
    for (int ps = 0; ps < 2; ps++) {
        const uint32_t sa = (uint32_t)(ps * A_H * 2), sb = (uint32_t)(ps * B_H * 2);
        #pragma unroll
        for (int i = 0; i < 4; i++)
            cpa16(dstA + sa + (uint32_t)(i * 64 * SK * 2),
                  Ab + (size_t)(r0c + i * 64) * lda + ps * BK + c0);
        #pragma unroll
        for (int i = 0; i < 2; i++)
            cpa16(dstB + sb + (uint32_t)(i * 64 * SK * 2),
                  Bb + (size_t)(r0c + i * 64) * ldb + ps * BK + c0);
        cpa_commit();
    }

    for (int t = 0; t < nit; t++) {
        const int buf = t % 3;
        cpa_wait1();
        __syncthreads();

        if (t + 2 < nit) {
            const int ps = (t + 2) % 3;
            const int k0 = (t + 2) * BK;
            const uint32_t sa = (uint32_t)(ps * A_H * 2), sb = (uint32_t)(ps * B_H * 2);
            #pragma unroll
            for (int i = 0; i < 4; i++)
                cpa16(dstA + sa + (uint32_t)(i * 64 * SK * 2),
                      Ab + (size_t)(r0c + i * 64) * lda + k0 + c0);
            #pragma unroll
            for (int i = 0; i < 2; i++)
                cpa16(dstB + sb + (uint32_t)(i * 64 * SK * 2),
                      Bb + (size_t)(r0c + i * 64) * ldb + k0 + c0);
        }
        cpa_commit();

        const uint32_t stA = as_u32 + (uint32_t)(buf * A_H * 2) + offA;
        const uint32_t stB = bs_u32 + (uint32_t)(buf * B_H * 2) + offB;
        #pragma unroll
        for (int ks = 0; ks < 2; ks++) {
            const uint32_t ko = (uint32_t)(ks * 16 * 2);
            uint32_t a[4][4], b[8][2];
            #pragma unroll
            for (int mt = 0; mt < 4; mt++)
                ldm4(a[mt][0], a[mt][1], a[mt][2], a[mt][3],
                     stA + (uint32_t)(mt * 16 * SK * 2) + ko);
            #pragma unroll
            for (int p = 0; p < 4; p++)
                ldm4(b[2*p][0], b[2*p][1], b[2*p+1][0], b[2*p+1][1],
                     stB + (uint32_t)(p * 16 * SK * 2) + ko);
            #pragma unroll
            for (int mt = 0; mt < 4; mt++)
                #pragma unroll
                for (int nt = 0; nt < 8; nt++)
                    mma_f16(acc[mt][nt], a[mt], b[nt][0], b[nt][1]);
        }
    }

    const int growb = blockIdx.y * BM + warpM * 64;
    const int gcolb = blockIdx.x * BN + warpN * 64;
    #pragma unroll
    for (int mt = 0; mt < 4; mt++) {
        #pragma unroll
        for (int half = 0; half < 2; half++) {
            const int row = growb + mt * 16 + half * 8 + g;
            __half* Crow = C + (size_t)row * ldc;
            #pragma unroll
            for (int nt = 0; nt < 8; nt++) {
                const int col = gcolb + nt * 8 + 2 * q4;
                float vx = acc[mt][nt][half * 2 + 0];
                float vy = acc[mt][nt][half * 2 + 1];
                if (BIAS) { vx += bias[col]; vy += bias[col + 1]; }
                if (RELU) { vx = fmaxf(vx, 0.f); vy = fmaxf(vy, 0.f); }
                *(uint32_t*)(Crow + col) = packh2(vx, vy);
            }
        }
    }
}

// ---------------------------------------------------------------------------
// hgemm: 128x128 CTA tile, 8 warps (4M x 2N), warp tile 32x64.
// Used for the N=1024 GEMMs (keeps grid >= 148).  fp32-out variants carry
// bias+residual.
// ---------------------------------------------------------------------------
template<bool BIAS, bool RELU, bool RES, bool OUTH>
__global__ __launch_bounds__(256, 2) void hgemm(
    const __half* __restrict__ A, int lda,
    const __half* __restrict__ B, int ldb,
    void* __restrict__ Cv, int ldc,
    const float* __restrict__ bias, const float* __restrict__ res, int K)
{
    constexpr int BM = 128, BN = 128, BK = 32, SK = 40, STG = 3;
    constexpr int TILE_H = BM * SK;
    extern __shared__ char smem_raw[];
    __half* As = (__half*)smem_raw;
    __half* Bs = (__half*)(smem_raw + STG * TILE_H * 2);

    const int tid = threadIdx.x;
    const int wid = tid >> 5, lane = tid & 31;
    const int warpM = wid & 3, warpN = wid >> 2;
    const int g = lane >> 2, q4 = lane & 3;

    const __half* Ab = A + (size_t)blockIdx.y * BM * lda;
    const __half* Bb = B + (size_t)blockIdx.x * BN * ldb;

    const int r0c = tid >> 2, c0 = (tid & 3) * 8;
    const uint32_t as_u32 = (uint32_t)__cvta_generic_to_shared(As);
    const uint32_t bs_u32 = (uint32_t)__cvta_generic_to_shared(Bs);
    const uint32_t dstA = as_u32 + (uint32_t)(r0c * SK + c0) * 2;
    const uint32_t dstB = bs_u32 + (uint32_t)(r0c * SK + c0) * 2;

    const int gsel = lane >> 3, rin = lane & 7;
    const uint32_t offA = (uint32_t)(((warpM * 32 + (gsel & 1) * 8 + rin) * SK
                                      + (gsel >> 1) * 8) * 2);
    const uint32_t offB = (uint32_t)(((warpN * 64 + (gsel >> 1) * 8 + rin) * SK
                                      + (gsel & 1) * 8) * 2);

    float acc[2][8][4];
    #pragma unroll
    for (int mt = 0; mt < 2; mt++)
        #pragma unroll
        for (int nt = 0; nt < 8; nt++)
            #pragma unroll
            for (int j = 0; j < 4; j++) acc[mt][nt][j] = 0.0f;

    const int nit = K / BK;

    #pragma unroll
    for (int ps = 0; ps < 2; ps++) {
        const uint32_t sb = (uint32_t)(ps * TILE_H * 2);
        cpa16(dstA + sb, Ab + (size_t)r0c * lda + ps * BK + c0);
        cpa16(dstA + sb + (uint32_t)(64 * SK * 2), Ab + (size_t)(r0c + 64) * lda + ps * BK + c0);
        cpa16(dstB + sb, Bb + (size_t)r0c * ldb + ps * BK + c0);
        cpa16(dstB + sb + (uint32_t)(64 * SK * 2), Bb + (size_t)(r0c + 64) * ldb + ps * BK + c0);
        cpa_commit();
    }

    for (int t = 0; t < nit; t++) {
        const int buf = t % 3;
        cpa_wait1();
        __syncthreads();

        if (t + 2 < nit) {
            const int ps = (t + 2) % 3;
            const int k0 = (t + 2) * BK;
            const uint32_t sb = (uint32_t)(ps * TILE_H * 2);
            cpa16(dstA + sb, Ab + (size_t)r0c * lda + k0 + c0);
            cpa16(dstA + sb + (uint32_t)(64 * SK * 2), Ab + (size_t)(r0c + 64) * lda + k0 + c0);
            cpa16(dstB + sb, Bb + (size_t)r0c * ldb + k0 + c0);
            cpa16(dstB + sb + (uint32_t)(64 * SK * 2), Bb + (size_t)(r0c + 64) * ldb + k0 + c0);
        }
        cpa_commit();

        const uint32_t stA = as_u32 + (uint32_t)(buf * TILE_H * 2) + offA;
        const uint32_t stB = bs_u32 + (uint32_t)(buf * TILE_H * 2) + offB;
        #pragma unroll
        for (int ks = 0; ks < 2; ks++) {
            const uint32_t ko = (uint32_t)(ks * 16 * 2);
            uint32_t a[2][4], b[8][2];
            ldm4(a[0][0], a[0][1], a[0][2], a[0][3], stA + ko);
            ldm4(a[1][0], a[1][1], a[1][2], a[1][3], stA + (uint32_t)(16 * SK * 2) + ko);
            #pragma unroll
            for (int p = 0; p < 4; p++)
                ldm4(b[2*p][0], b[2*p][1], b[2*p+1][0], b[2*p+1][1],
                     stB + (uint32_t)(p * 16 * SK * 2) + ko);
            #pragma unroll
            for (int mt = 0; mt < 2; mt++)
                #pragma unroll
                for (int nt = 0; nt < 8; nt++)
                    mma_f16(acc[mt][nt], a[mt], b[nt][0], b[nt][1]);
        }
    }

    const int growb = blockIdx.y * BM + warpM * 32;
    const int gcolb = blockIdx.x * BN + warpN * 64;
    #pragma unroll
    for (int mt = 0; mt < 2; mt++) {
        #pragma unroll
        for (int half = 0; half < 2; half++) {
            const int row = growb + mt * 16 + half * 8 + g;
            #pragma unroll
            for (int nt = 0; nt < 8; nt++) {
                const int col = gcolb + nt * 8 + 2 * q4;
                float vx = acc[mt][nt][half * 2 + 0];
                float vy = acc[mt][nt][half * 2 + 1];
                if (BIAS) { vx += bias[col]; vy += bias[col + 1]; }
                if (RES) {
                    const float* rr = res + (size_t)row * ldc + col;
                    vx += rr[0]; vy += rr[1];
                }
                if (RELU) { vx = fmaxf(vx, 0.f); vy = fmaxf(vy, 0.f); }
                if (OUTH) {
                    *(uint32_t*)((__half*)Cv + (size_t)row * ldc + col) = packh2(vx, vy);
                } else {
                    *(float2*)((float*)Cv + (size_t)row * ldc + col) = make_float2(vx, vy);
                }
            }
        }
    }
}

// ---------------------------------------------------------------------------
// Flash attention over packed QKV (ld = 3*DM).
// ---------------------------------------------------------------------------
#define QKVLD (3 * DM)
__global__ __launch_bounds__(256) void flash_attn(
    const __half* __restrict__ QKV, __half* __restrict__ Og)
{
    __shared__ __half Ksm[64][72];
    __shared__ __half Vt [64][72];

    const int tid = threadIdx.x, wid = tid >> 5, lane = tid & 31;
    const int g = lane >> 2, q4 = lane & 3;
    const int h = blockIdx.y, n = blockIdx.z;
    const int q0 = blockIdx.x * 128 + wid * 16;
    const size_t base = (size_t)n * S * QKVLD + h * HD;
    const __half* Qg = QKV + base;
    const __half* Kg = QKV + base + DM;
    const __half* Vg = QKV + base + 2 * DM;

    uint32_t qf[4][4];
    {
        const __half* r0 = Qg + (size_t)(q0 + g) * QKVLD;
        const __half* r1 = Qg + (size_t)(q0 + g + 8) * QKVLD;
        #pragma unroll
        for (int ks = 0; ks < 4; ks++) {
            const int c = ks * 16 + 2 * q4;
            qf[ks][0] = *(const uint32_t*)(r0 + c);
            qf[ks][1] = *(const uint32_t*)(r1 + c);
            qf[ks][2] = *(const uint32_t*)(r0 + c + 8);
            qf[ks][3] = *(const uint32_t*)(r1 + c + 8);
        }
    }

    float o[8][4];
    #pragma unroll
    for (int nd = 0; nd < 8; nd++)
        #pragma unroll
        for (int j = 0; j < 4; j++) o[nd][j] = 0.0f;
    float m0 = -INFINITY, m1 = -INFINITY, l0 = 0.0f, l1 = 0.0f;

    for (int kv = 0; kv < S; kv += 64) {
        #pragma unroll
        for (int i = 0; i < 4; i++) {
            const int idx = tid + i * 256;
            const int r = idx >> 4, cq = idx & 15;
            *(uint2*)&Ksm[r][cq * 4] =
                *(const uint2*)(Kg + (size_t)(kv + r) * QKVLD + cq * 4);
            __half vv[4];
            *(uint2*)vv = *(const uint2*)(Vg + (size_t)(kv + r) * QKVLD + cq * 4);
            Vt[cq * 4 + 0][r] = vv[0];
            Vt[cq * 4 + 1][r] = vv[1];
            Vt[cq * 4 + 2][r] = vv[2];
            Vt[cq * 4 + 3][r] = vv[3];
        }
        __syncthreads();

        float c[8][4];
        #pragma unroll
        for (int nt = 0; nt < 8; nt++)
            #pragma unroll
            for (int j = 0; j < 4; j++) c[nt][j] = 0.0f;
        #pragma unroll
        for (int ks = 0; ks < 4; ks++) {
            const int kk = ks * 16 + 2 * q4;
            #pragma unroll
            for (int nt = 0; nt < 8; nt++) {
                const uint32_t b0 = *(const uint32_t*)&Ksm[nt * 8 + g][kk];
                const uint32_t b1 = *(const uint32_t*)&Ksm[nt * 8 + g][kk + 8];
                mma_f16(c[nt], qf[ks], b0, b1);
            }
        }

        float mx0 = -INFINITY, mx1 = -INFINITY;
        #pragma unroll
        for (int nt = 0; nt < 8; nt++) {
            mx0 = fmaxf(mx0, fmaxf(c[nt][0], c[nt][1]));
            mx1 = fmaxf(mx1, fmaxf(c[nt][2], c[nt][3]));
        }
        mx0 = fmaxf(mx0, __shfl_xor_sync(0xffffffffu, mx0, 1));
        mx0 = fmaxf(mx0, __shfl_xor_sync(0xffffffffu, mx0, 2));
        mx1 = fmaxf(mx1, __shfl_xor_sync(0xffffffffu, mx1, 1));
        mx1 = fmaxf(mx1, __shfl_xor_sync(0xffffffffu, mx1, 2));
        const float nm0 = fmaxf(m0, mx0), nm1 = fmaxf(m1, mx1);
        const float r0 = __expf((m0 - nm0) * 0.125f);
        const float r1 = __expf((m1 - nm1) * 0.125f);
        m0 = nm0; m1 = nm1;

        float s0 = 0.0f, s1 = 0.0f;
        #pragma unroll
        for (int nt = 0; nt < 8; nt++) {
            c[nt][0] = __expf((c[nt][0] - m0) * 0.125f);
            c[nt][1] = __expf((c[nt][1] - m0) * 0.125f);
            c[nt][2] = __expf((c[nt][2] - m1) * 0.125f);
            c[nt][3] = __expf((c[nt][3] - m1) * 0.125f);
            s0 += c[nt][0] + c[nt][1];
            s1 += c[nt][2] + c[nt][3];
        }
        s0 += __shfl_xor_sync(0xffffffffu, s0, 1);
        s0 += __shfl_xor_sync(0xffffffffu, s0, 2);
        s1 += __shfl_xor_sync(0xffffffffu, s1, 1);
        s1 += __shfl_xor_sync(0xffffffffu, s1, 2);
        l0 = l0 * r0 + s0;
        l1 = l1 * r1 + s1;

        #pragma unroll
        for (int nd = 0; nd < 8; nd++) {
            o[nd][0] *= r0; o[nd][1] *= r0;
            o[nd][2] *= r1; o[nd][3] *= r1;
        }

        #pragma unroll
        for (int ks2 = 0; ks2 < 4; ks2++) {
            uint32_t pa[4];
            pa[0] = packh2(c[2 * ks2][0],     c[2 * ks2][1]);
            pa[1] = packh2(c[2 * ks2][2],     c[2 * ks2][3]);
            pa[2] = packh2(c[2 * ks2 + 1][0], c[2 * ks2 + 1][1]);
            pa[3] = packh2(c[2 * ks2 + 1][2], c[2 * ks2 + 1][3]);
            const int kk = ks2 * 16 + 2 * q4;
            #pragma unroll
            for (int nd = 0; nd < 8; nd++) {
                const uint32_t b0 = *(const uint32_t*)&Vt[nd * 8 + g][kk];
                const uint32_t b1 = *(const uint32_t*)&Vt[nd * 8 + g][kk + 8];
                mma_f16(o[nd], pa, b0, b1);
            }
        }
        __syncthreads();
    }

    const float i0 = 1.0f / l0, i1 = 1.0f / l1;
    __half* o0 = Og + (size_t)n * S * DM + h * HD + (size_t)(q0 + g) * DM;
    __half* o1 = o0 + (size_t)8 * DM;
    #pragma unroll
    for (int nd = 0; nd < 8; nd++) {
        const int col = nd * 8 + 2 * q4;
        *(uint32_t*)(o0 + col) = packh2(o[nd][0] * i0, o[nd][1] * i0);
        *(uint32_t*)(o1 + col) = packh2(o[nd][2] * i1, o[nd][3] * i1);
    }
}

// ---------------------------------------------------------------------------
// Transposes fp32 [rows][cols] -> fp16 [cols][rows]
// ---------------------------------------------------------------------------
__global__ __launch_bounds__(256) void transpose_h(
    const float* __restrict__ in, int rows, int cols, __half* __restrict__ out)
{
    __shared__ float t[32][33];
    const int c0 = blockIdx.x * 32, r0 = blockIdx.y * 32;
    const int tx = threadIdx.x & 31, ty = threadIdx.x >> 5;
    #pragma unroll
    for (int i = 0; i < 32; i += 8)
        t[ty + i][tx] = in[(size_t)(r0 + ty + i) * cols + c0 + tx];
    __syncthreads();
    #pragma unroll
    for (int i = 0; i < 32; i += 8)
        out[(size_t)(c0 + ty + i) * rows + r0 + tx] = __float2half(t[tx][ty + i]);
}

// 4 DM x DM weight transposes batched in one launch (z selects the matrix).
__global__ __launch_bounds__(256) void transpose_h4(
    const float* __restrict__ s0, const float* __restrict__ s1,
    const float* __restrict__ s2, const float* __restrict__ s3,
    __half* __restrict__ d0, __half* __restrict__ d1,
    __half* __restrict__ d2, __half* __restrict__ d3)
{
    __shared__ float t[32][33];
    const float* in;
    __half* out;
    switch (blockIdx.z) {
        case 0: in = s0; out = d0; break;
        case 1: in = s1; out = d1; break;
        case 2: in = s2; out = d2; break;
        default: in = s3; out = d3; break;
    }
    const int c0 = blockIdx.x * 32, r0 = blockIdx.y * 32;
    const int tx = threadIdx.x & 31, ty = threadIdx.x >> 5;
    #pragma unroll
    for (int i = 0; i < 32; i += 8)
        t[ty + i][tx] = in[(size_t)(r0 + ty + i) * DM + c0 + tx];
    __syncthreads();
    #pragma unroll
    for (int i = 0; i < 32; i += 8)
        out[(size_t)(c0 + ty + i) * DM + r0 + tx] = __float2half(t[tx][ty + i]);
}

// ---------------------------------------------------------------------------
// LayerNorm fp32 in -> fp16 out.
// ---------------------------------------------------------------------------
__global__ __launch_bounds__(256) void ln_h(
    const float* __restrict__ x, const float* __restrict__ g,
    const float* __restrict__ b, __half* __restrict__ y)
{
    const int row = blockIdx.x, t = threadIdx.x;
    float4 v = ((const float4*)(x + (size_t)row * DM))[t];
    float sum = v.x + v.y + v.z + v.w;
    float sq  = v.x*v.x + v.y*v.y + v.z*v.z + v.w*v.w;
    __shared__ float s1[256], s2[256];
    s1[t] = sum; s2[t] = sq;
    __syncthreads();
    #pragma unroll
    for (int st = 128; st > 0; st >>= 1) {
        if (t < st) { s1[t] += s1[t + st]; s2[t] += s2[t + st]; }
        __syncthreads();
    }
    const float mu  = s1[0] * (1.0f / DM);
    const float var = s2[0] * (1.0f / DM) - mu * mu;
    const float inv = rsqrtf(var + LN_EPS);
    const float4 gv = ((const float4*)g)[t];
    const float4 bv = ((const float4*)b)[t];
    uint2 ov;
    ov.x = packh2((v.x - mu) * inv * gv.x + bv.x, (v.y - mu) * inv * gv.y + bv.y);
    ov.y = packh2((v.z - mu) * inv * gv.z + bv.z, (v.w - mu) * inv * gv.w + bv.w);
    ((uint2*)(y + (size_t)row * DM))[t] = ov;
}

// ---------------------------------------------------------------------------
// Launch
// ---------------------------------------------------------------------------
extern "C" void kernel_launch(void* const* d_in, const int* in_sizes, int n_in,
                              void* d_out, int out_size)
{
    const float* x    = (const float*)d_in[0];
    const float* w_q  = (const float*)d_in[2];
    const float* w_k  = (const float*)d_in[3];
    const float* w_v  = (const float*)d_in[4];
    const float* w_0  = (const float*)d_in[5];
    const float* b_0  = (const float*)d_in[6];
    const float* w_1  = (const float*)d_in[7];
    const float* b_1  = (const float*)d_in[8];
    const float* w_2  = (const float*)d_in[9];
    const float* b_2  = (const float*)d_in[10];
    const float* g_1  = (const float*)d_in[11];
    const float* be_1 = (const float*)d_in[12];
    const float* g_2  = (const float*)d_in[13];
    const float* be_2 = (const float*)d_in[14];
    float* out = (float*)d_out;

    __half *xnh, *qkv, *aoh, *ffh, *wqkvt, *w0t, *w1t, *w2t;
    float* x2;
    cudaGetSymbolAddress((void**)&xnh, g_xnh);
    cudaGetSymbolAddress((void**)&qkv, g_qkv);
    cudaGetSymbolAddress((void**)&aoh, g_aoh);
    cudaGetSymbolAddress((void**)&ffh, g_ffh);
    cudaGetSymbolAddress((void**)&x2,  g_x2);
    cudaGetSymbolAddress((void**)&wqkvt, g_wqkvt);
    cudaGetSymbolAddress((void**)&w0t, g_w0t);
    cudaGetSymbolAddress((void**)&w1t, g_w1t);
    cudaGetSymbolAddress((void**)&w2t, g_w2t);

    const int DSMEM   = 3 * 128 * 40 * 2 * 2;              // 61440
    const int DSMEM256 = 3 * (256 + 128) * 40 * 2;         // 92160
    static bool attr_done = false;
    if (!attr_done) {
        cudaFuncSetAttribute(hgemm256<false,false>,
                             cudaFuncAttributeMaxDynamicSharedMemorySize, DSMEM256);
        cudaFuncSetAttribute(hgemm256<true,true>,
                             cudaFuncAttributeMaxDynamicSharedMemorySize, DSMEM256);
        cudaFuncSetAttribute(hgemm<true,false,true,false>,
                             cudaFuncAttributeMaxDynamicSharedMemorySize, DSMEM);
        attr_done = true;
    }

    // Weight transpose+convert: W[K][N] fp32 -> Wt[N][K] fp16 (QKV packed)
    transpose_h4<<<dim3(DM/32, DM/32, 4), 256>>>(
        w_q, w_k, w_v, w_0,
        wqkvt, wqkvt + (size_t)DM * DM, wqkvt + (size_t)2 * DM * DM, w0t);
    transpose_h<<<dim3(DFF/32, DM/32),  256>>>(w_1, DM, DFF, w1t);
    transpose_h<<<dim3(DM/32,  DFF/32), 256>>>(w_2, DFF, DM, w2t);

    // LN1 -> fp16
    ln_h<<<TOK, 256>>>(x, g_1, be_1, xnh);

    // Fused QKV projection: [4096, 3072] = xnh @ Wqkv^T  (256-row tiles)
    hgemm256<false,false><<<dim3(24, 16), 256, DSMEM256>>>(
        xnh, DM, wqkvt, DM, qkv, 3 * DM, nullptr, DM);

    // Fused attention
    flash_attn<<<dim3(S/128, NH, NB), 256>>>(qkv, aoh);

    // x2 = x + ao @ W0 + b0   (fp32 out)
    hgemm<true,false,true,false><<<dim3(8, 32), 256, DSMEM>>>(
        aoh, DM, w0t, DM, x2, DM, b_0, x, DM);

    // LN2 -> fp16
    ln_h<<<TOK, 256>>>(x2, g_2, be_2, xnh);

    // ff = relu(xn @ W1 + b1)  (fp16 out, 256-row tiles)
    hgemm256<true,true><<<dim3(32, 16), 256, DSMEM256>>>(
        xnh, DM, w1t, DM, ffh, DFF, b_1, DM);

    // out = x2 + ff @ W2 + b2  (fp32 out)
    hgemm<true,false,true,false><<<dim3(8, 32), 256, DSMEM>>>(
        ffh, DFF, w2t, DFF, out, DM, b_2, x2, DFF);
}

// round 11
// speedup vs baseline: 1.0018x; 1.0018x over previous
#include <cuda_runtime.h>
#include <cuda_fp16.h>
#include <cstdint>
#include <math.h>

// ---------------------------------------------------------------------------
// Problem constants
// ---------------------------------------------------------------------------
#define NB   2
#define S    2048
#define DM   1024
#define NH   16
#define HD   64
#define DFF  4096
#define TOK  (NB * S)
#define LN_EPS 1e-5f

// ---------------------------------------------------------------------------
// Scratch (static device globals; no runtime allocation allowed)
// ---------------------------------------------------------------------------
__device__ __half g_xnh [(size_t)TOK * DM];
__device__ __half g_qkv [(size_t)TOK * 3 * DM];   // packed Q|K|V, ld = 3072
__device__ __half g_aoh [(size_t)TOK * DM];
__device__ __half g_ffh [(size_t)TOK * DFF];
__device__ float  g_x2  [(size_t)TOK * DM];
__device__ __half g_wqkvt[(size_t)3 * DM * DM];   // [3072][1024] K-major
__device__ __half g_w0t [(size_t)DM * DM];
__device__ __half g_w1t [(size_t)DFF * DM];
__device__ __half g_w2t [(size_t)DM * DFF];

// ---------------------------------------------------------------------------
// Helpers
// ---------------------------------------------------------------------------
__device__ __forceinline__ void mma_f16(float* c, const uint32_t* a,
                                        uint32_t b0, uint32_t b1) {
    asm volatile(
        "mma.sync.aligned.m16n8k16.row.col.f32.f16.f16.f32 "
        "{%0,%1,%2,%3}, {%4,%5,%6,%7}, {%8,%9}, {%0,%1,%2,%3};"
        : "+f"(c[0]), "+f"(c[1]), "+f"(c[2]), "+f"(c[3])
        : "r"(a[0]), "r"(a[1]), "r"(a[2]), "r"(a[3]), "r"(b0), "r"(b1));
}
__device__ __forceinline__ uint32_t packh2(float x, float y) {
    __half2 h = __floats2half2_rn(x, y);
    return *(uint32_t*)&h;
}
__device__ __forceinline__ void cpa16(uint32_t dst, const void* src) {
    asm volatile("cp.async.cg.shared.global [%0], [%1], 16;" :: "r"(dst), "l"(src));
}
__device__ __forceinline__ void cpa_commit() {
    asm volatile("cp.async.commit_group;" ::: "memory");
}
__device__ __forceinline__ void cpa_wait1() {
    asm volatile("cp.async.wait_group 1;" ::: "memory");
}
__device__ __forceinline__ void ldm4(uint32_t& r0, uint32_t& r1, uint32_t& r2,
                                     uint32_t& r3, uint32_t addr) {
    asm volatile("ldmatrix.sync.aligned.m8n8.x4.shared.b16 {%0,%1,%2,%3}, [%4];"
                 : "=r"(r0), "=r"(r1), "=r"(r2), "=r"(r3) : "r"(addr));
}

// ---------------------------------------------------------------------------
// hgemm256: 256x128 CTA tile, 8 warps (4M x 2N), warp tile 64x64.
// fp16 in (A [M][K], B [N][K] K-major), fp16 out, optional bias/relu.
// cp.async 3-stage pipeline, ldmatrix fragments, SK=40 padding.
// ---------------------------------------------------------------------------
template<bool BIAS, bool RELU>
__global__ __launch_bounds__(256) void hgemm256(
    const __half* __restrict__ A, int lda,
    const __half* __restrict__ B, int ldb,
    __half* __restrict__ C, int ldc,
    const float* __restrict__ bias, int K)
{
    constexpr int BM = 256, BN = 128, BK = 32, SK = 40, STG = 3;
    constexpr int A_H = BM * SK, B_H = BN * SK;          // halves per stage
    extern __shared__ char smem_raw[];
    __half* As = (__half*)smem_raw;                      // [STG][BM][SK]
    __half* Bs = (__half*)(smem_raw + STG * A_H * 2);    // [STG][BN][SK]

    const int tid = threadIdx.x;
    const int wid = tid >> 5, lane = tid & 31;
    const int warpM = wid & 3, warpN = wid >> 2;
    const int g = lane >> 2, q4 = lane & 3;

    const __half* Ab = A + (size_t)blockIdx.y * BM * lda;
    const __half* Bb = B + (size_t)blockIdx.x * BN * ldb;

    const int r0c = tid >> 2, c0 = (tid & 3) * 8;
    const uint32_t as_u32 = (uint32_t)__cvta_generic_to_shared(As);
    const uint32_t bs_u32 = (uint32_t)__cvta_generic_to_shared(Bs);
    const uint32_t dstA = as_u32 + (uint32_t)(r0c * SK + c0) * 2;
    const uint32_t dstB = bs_u32 + (uint32_t)(r0c * SK + c0) * 2;

    const int gsel = lane >> 3, rin = lane & 7;
    const uint32_t offA = (uint32_t)(((warpM * 64 + (gsel & 1) * 8 + rin) * SK
                                      + (gsel >> 1) * 8) * 2);
    const uint32_t offB = (uint32_t)(((warpN * 64 + (gsel >> 1) * 8 + rin) * SK
                                      + (gsel & 1) * 8) * 2);

    float acc[4][8][4];
    #pragma unroll
    for (int mt = 0; mt < 4; mt++)
        #pragma unroll
        for (int nt = 0; nt < 8; nt++)
            #pragma unroll
            for (int j = 0; j < 4; j++) acc[mt][nt][j] = 0.0f;

    const int nit = K / BK;

    #pragma unroll
    for (int ps = 0; ps < 2; ps++) {
        const uint32_t sa = (uint32_t)(ps * A_H * 2), sb = (uint32_t)(ps * B_H * 2);
        #pragma unroll
        for (int i = 0; i < 4; i++)
            cpa16(dstA + sa + (uint32_t)(i * 64 * SK * 2),
                  Ab + (size_t)(r0c + i * 64) * lda + ps * BK + c0);
        #pragma unroll
        for (int i = 0; i < 2; i++)
            cpa16(dstB + sb + (uint32_t)(i * 64 * SK * 2),
                  Bb + (size_t)(r0c + i * 64) * ldb + ps * BK + c0);
        cpa_commit();
    }

    for (int t = 0; t < nit; t++) {
        const int buf = t % 3;
        cpa_wait1();
        __syncthreads();

        if (t + 2 < nit) {
            const int ps = (t + 2) % 3;
            const int k0 = (t + 2) * BK;
            const uint32_t sa = (uint32_t)(ps * A_H * 2), sb = (uint32_t)(ps * B_H * 2);
            #pragma unroll
            for (int i = 0; i < 4; i++)
                cpa16(dstA + sa + (uint32_t)(i * 64 * SK * 2),
                      Ab + (size_t)(r0c + i * 64) * lda + k0 + c0);
            #pragma unroll
            for (int i = 0; i < 2; i++)
                cpa16(dstB + sb + (uint32_t)(i * 64 * SK * 2),
                      Bb + (size_t)(r0c + i * 64) * ldb + k0 + c0);
        }
        cpa_commit();

        const uint32_t stA = as_u32 + (uint32_t)(buf * A_H * 2) + offA;
        const uint32_t stB = bs_u32 + (uint32_t)(buf * B_H * 2) + offB;
        #pragma unroll
        for (int ks = 0; ks < 2; ks++) {
            const uint32_t ko = (uint32_t)(ks * 16 * 2);
            uint32_t a[4][4], b[8][2];
            #pragma unroll
            for (int mt = 0; mt < 4; mt++)
                ldm4(a[mt][0], a[mt][1], a[mt][2], a[mt][3],
                     stA + (uint32_t)(mt * 16 * SK * 2) + ko);
            #pragma unroll
            for (int p = 0; p < 4; p++)
                ldm4(b[2*p][0], b[2*p][1], b[2*p+1][0], b[2*p+1][1],
                     stB + (uint32_t)(p * 16 * SK * 2) + ko);
            #pragma unroll
            for (int mt = 0; mt < 4; mt++)
                #pragma unroll
                for (int nt = 0; nt < 8; nt++)
                    mma_f16(acc[mt][nt], a[mt], b[nt][0], b[nt][1]);
        }
    }

    const int growb = blockIdx.y * BM + warpM * 64;
    const int gcolb = blockIdx.x * BN + warpN * 64;
    #pragma unroll
    for (int mt = 0; mt < 4; mt++) {
        #pragma unroll
        for (int half = 0; half < 2; half++) {
            const int row = growb + mt * 16 + half * 8 + g;
            __half* Crow = C + (size_t)row * ldc;
            #pragma unroll
            for (int nt = 0; nt < 8; nt++) {
                const int col = gcolb + nt * 8 + 2 * q4;
                float vx = acc[mt][nt][half * 2 + 0];
                float vy = acc[mt][nt][half * 2 + 1];
                if (BIAS) { vx += bias[col]; vy += bias[col + 1]; }
                if (RELU) { vx = fmaxf(vx, 0.f); vy = fmaxf(vy, 0.f); }
                *(uint32_t*)(Crow + col) = packh2(vx, vy);
            }
        }
    }
}

// ---------------------------------------------------------------------------
// hgemm: 128x128 CTA tile, 8 warps (4M x 2N), warp tile 32x64.
// Used for the N=1024 GEMMs (keeps grid >= 148).  fp32-out variants carry
// bias+residual.
// ---------------------------------------------------------------------------
template<bool BIAS, bool RELU, bool RES, bool OUTH>
__global__ __launch_bounds__(256, 2) void hgemm(
    const __half* __restrict__ A, int lda,
    const __half* __restrict__ B, int ldb,
    void* __restrict__ Cv, int ldc,
    const float* __restrict__ bias, const float* __restrict__ res, int K)
{
    constexpr int BM = 128, BN = 128, BK = 32, SK = 40, STG = 3;
    constexpr int TILE_H = BM * SK;
    extern __shared__ char smem_raw[];
    __half* As = (__half*)smem_raw;
    __half* Bs = (__half*)(smem_raw + STG * TILE_H * 2);

    const int tid = threadIdx.x;
    const int wid = tid >> 5, lane = tid & 31;
    const int warpM = wid & 3, warpN = wid >> 2;
    const int g = lane >> 2, q4 = lane & 3;

    const __half* Ab = A + (size_t)blockIdx.y * BM * lda;
    const __half* Bb = B + (size_t)blockIdx.x * BN * ldb;

    const int r0c = tid >> 2, c0 = (tid & 3) * 8;
    const uint32_t as_u32 = (uint32_t)__cvta_generic_to_shared(As);
    const uint32_t bs_u32 = (uint32_t)__cvta_generic_to_shared(Bs);
    const uint32_t dstA = as_u32 + (uint32_t)(r0c * SK + c0) * 2;
    const uint32_t dstB = bs_u32 + (uint32_t)(r0c * SK + c0) * 2;

    const int gsel = lane >> 3, rin = lane & 7;
    const uint32_t offA = (uint32_t)(((warpM * 32 + (gsel & 1) * 8 + rin) * SK
                                      + (gsel >> 1) * 8) * 2);
    const uint32_t offB = (uint32_t)(((warpN * 64 + (gsel >> 1) * 8 + rin) * SK
                                      + (gsel & 1) * 8) * 2);

    float acc[2][8][4];
    #pragma unroll
    for (int mt = 0; mt < 2; mt++)
        #pragma unroll
        for (int nt = 0; nt < 8; nt++)
            #pragma unroll
            for (int j = 0; j < 4; j++) acc[mt][nt][j] = 0.0f;

    const int nit = K / BK;

    #pragma unroll
    for (int ps = 0; ps < 2; ps++) {
        const uint32_t sb = (uint32_t)(ps * TILE_H * 2);
        cpa16(dstA + sb, Ab + (size_t)r0c * lda + ps * BK + c0);
        cpa16(dstA + sb + (uint32_t)(64 * SK * 2), Ab + (size_t)(r0c + 64) * lda + ps * BK + c0);
        cpa16(dstB + sb, Bb + (size_t)r0c * ldb + ps * BK + c0);
        cpa16(dstB + sb + (uint32_t)(64 * SK * 2), Bb + (size_t)(r0c + 64) * ldb + ps * BK + c0);
        cpa_commit();
    }

    for (int t = 0; t < nit; t++) {
        const int buf = t % 3;
        cpa_wait1();
        __syncthreads();

        if (t + 2 < nit) {
            const int ps = (t + 2) % 3;
            const int k0 = (t + 2) * BK;
            const uint32_t sb = (uint32_t)(ps * TILE_H * 2);
            cpa16(dstA + sb, Ab + (size_t)r0c * lda + k0 + c0);
            cpa16(dstA + sb + (uint32_t)(64 * SK * 2), Ab + (size_t)(r0c + 64) * lda + k0 + c0);
            cpa16(dstB + sb, Bb + (size_t)r0c * ldb + k0 + c0);
            cpa16(dstB + sb + (uint32_t)(64 * SK * 2), Bb + (size_t)(r0c + 64) * ldb + k0 + c0);
        }
        cpa_commit();

        const uint32_t stA = as_u32 + (uint32_t)(buf * TILE_H * 2) + offA;
        const uint32_t stB = bs_u32 + (uint32_t)(buf * TILE_H * 2) + offB;
        #pragma unroll
        for (int ks = 0; ks < 2; ks++) {
            const uint32_t ko = (uint32_t)(ks * 16 * 2);
            uint32_t a[2][4], b[8][2];
            ldm4(a[0][0], a[0][1], a[0][2], a[0][3], stA + ko);
            ldm4(a[1][0], a[1][1], a[1][2], a[1][3], stA + (uint32_t)(16 * SK * 2) + ko);
            #pragma unroll
            for (int p = 0; p < 4; p++)
                ldm4(b[2*p][0], b[2*p][1], b[2*p+1][0], b[2*p+1][1],
                     stB + (uint32_t)(p * 16 * SK * 2) + ko);
            #pragma unroll
            for (int mt = 0; mt < 2; mt++)
                #pragma unroll
                for (int nt = 0; nt < 8; nt++)
                    mma_f16(acc[mt][nt], a[mt], b[nt][0], b[nt][1]);
        }
    }

    const int growb = blockIdx.y * BM + warpM * 32;
    const int gcolb = blockIdx.x * BN + warpN * 64;
    #pragma unroll
    for (int mt = 0; mt < 2; mt++) {
        #pragma unroll
        for (int half = 0; half < 2; half++) {
            const int row = growb + mt * 16 + half * 8 + g;
            #pragma unroll
            for (int nt = 0; nt < 8; nt++) {
                const int col = gcolb + nt * 8 + 2 * q4;
                float vx = acc[mt][nt][half * 2 + 0];
                float vy = acc[mt][nt][half * 2 + 1];
                if (BIAS) { vx += bias[col]; vy += bias[col + 1]; }
                if (RES) {
                    const float* rr = res + (size_t)row * ldc + col;
                    vx += rr[0]; vy += rr[1];
                }
                if (RELU) { vx = fmaxf(vx, 0.f); vy = fmaxf(vy, 0.f); }
                if (OUTH) {
                    *(uint32_t*)((__half*)Cv + (size_t)row * ldc + col) = packh2(vx, vy);
                } else {
                    *(float2*)((float*)Cv + (size_t)row * ldc + col) = make_float2(vx, vy);
                }
            }
        }
    }
}

// ---------------------------------------------------------------------------
// Flash attention over packed QKV (ld = 3*DM).
// ---------------------------------------------------------------------------
#define QKVLD (3 * DM)
__global__ __launch_bounds__(256) void flash_attn(
    const __half* __restrict__ QKV, __half* __restrict__ Og)
{
    __shared__ __half Ksm[64][72];
    __shared__ __half Vt [64][72];

    const int tid = threadIdx.x, wid = tid >> 5, lane = tid & 31;
    const int g = lane >> 2, q4 = lane & 3;
    const int h = blockIdx.y, n = blockIdx.z;
    const int q0 = blockIdx.x * 128 + wid * 16;
    const size_t base = (size_t)n * S * QKVLD + h * HD;
    const __half* Qg = QKV + base;
    const __half* Kg = QKV + base + DM;
    const __half* Vg = QKV + base + 2 * DM;

    uint32_t qf[4][4];
    {
        const __half* r0 = Qg + (size_t)(q0 + g) * QKVLD;
        const __half* r1 = Qg + (size_t)(q0 + g + 8) * QKVLD;
        #pragma unroll
        for (int ks = 0; ks < 4; ks++) {
            const int c = ks * 16 + 2 * q4;
            qf[ks][0] = *(const uint32_t*)(r0 + c);
            qf[ks][1] = *(const uint32_t*)(r1 + c);
            qf[ks][2] = *(const uint32_t*)(r0 + c + 8);
            qf[ks][3] = *(const uint32_t*)(r1 + c + 8);
        }
    }

    float o[8][4];
    #pragma unroll
    for (int nd = 0; nd < 8; nd++)
        #pragma unroll
        for (int j = 0; j < 4; j++) o[nd][j] = 0.0f;
    float m0 = -INFINITY, m1 = -INFINITY, l0 = 0.0f, l1 = 0.0f;

    for (int kv = 0; kv < S; kv += 64) {
        #pragma unroll
        for (int i = 0; i < 4; i++) {
            const int idx = tid + i * 256;
            const int r = idx >> 4, cq = idx & 15;
            *(uint2*)&Ksm[r][cq * 4] =
                *(const uint2*)(Kg + (size_t)(kv + r) * QKVLD + cq * 4);
            __half vv[4];
            *(uint2*)vv = *(const uint2*)(Vg + (size_t)(kv + r) * QKVLD + cq * 4);
            Vt[cq * 4 + 0][r] = vv[0];
            Vt[cq * 4 + 1][r] = vv[1];
            Vt[cq * 4 + 2][r] = vv[2];
            Vt[cq * 4 + 3][r] = vv[3];
        }
        __syncthreads();

        float c[8][4];
        #pragma unroll
        for (int nt = 0; nt < 8; nt++)
            #pragma unroll
            for (int j = 0; j < 4; j++) c[nt][j] = 0.0f;
        #pragma unroll
        for (int ks = 0; ks < 4; ks++) {
            const int kk = ks * 16 + 2 * q4;
            #pragma unroll
            for (int nt = 0; nt < 8; nt++) {
                const uint32_t b0 = *(const uint32_t*)&Ksm[nt * 8 + g][kk];
                const uint32_t b1 = *(const uint32_t*)&Ksm[nt * 8 + g][kk + 8];
                mma_f16(c[nt], qf[ks], b0, b1);
            }
        }

        float mx0 = -INFINITY, mx1 = -INFINITY;
        #pragma unroll
        for (int nt = 0; nt < 8; nt++) {
            mx0 = fmaxf(mx0, fmaxf(c[nt][0], c[nt][1]));
            mx1 = fmaxf(mx1, fmaxf(c[nt][2], c[nt][3]));
        }
        mx0 = fmaxf(mx0, __shfl_xor_sync(0xffffffffu, mx0, 1));
        mx0 = fmaxf(mx0, __shfl_xor_sync(0xffffffffu, mx0, 2));
        mx1 = fmaxf(mx1, __shfl_xor_sync(0xffffffffu, mx1, 1));
        mx1 = fmaxf(mx1, __shfl_xor_sync(0xffffffffu, mx1, 2));
        const float nm0 = fmaxf(m0, mx0), nm1 = fmaxf(m1, mx1);
        const float r0 = __expf((m0 - nm0) * 0.125f);
        const float r1 = __expf((m1 - nm1) * 0.125f);
        m0 = nm0; m1 = nm1;

        float s0 = 0.0f, s1 = 0.0f;
        #pragma unroll
        for (int nt = 0; nt < 8; nt++) {
            c[nt][0] = __expf((c[nt][0] - m0) * 0.125f);
            c[nt][1] = __expf((c[nt][1] - m0) * 0.125f);
            c[nt][2] = __expf((c[nt][2] - m1) * 0.125f);
            c[nt][3] = __expf((c[nt][3] - m1) * 0.125f);
            s0 += c[nt][0] + c[nt][1];
            s1 += c[nt][2] + c[nt][3];
        }
        s0 += __shfl_xor_sync(0xffffffffu, s0, 1);
        s0 += __shfl_xor_sync(0xffffffffu, s0, 2);
        s1 += __shfl_xor_sync(0xffffffffu, s1, 1);
        s1 += __shfl_xor_sync(0xffffffffu, s1, 2);
        l0 = l0 * r0 + s0;
        l1 = l1 * r1 + s1;

        #pragma unroll
        for (int nd = 0; nd < 8; nd++) {
            o[nd][0] *= r0; o[nd][1] *= r0;
            o[nd][2] *= r1; o[nd][3] *= r1;
        }

        #pragma unroll
        for (int ks2 = 0; ks2 < 4; ks2++) {
            uint32_t pa[4];
            pa[0] = packh2(c[2 * ks2][0],     c[2 * ks2][1]);
            pa[1] = packh2(c[2 * ks2][2],     c[2 * ks2][3]);
            pa[2] = packh2(c[2 * ks2 + 1][0], c[2 * ks2 + 1][1]);
            pa[3] = packh2(c[2 * ks2 + 1][2], c[2 * ks2 + 1][3]);
            const int kk = ks2 * 16 + 2 * q4;
            #pragma unroll
            for (int nd = 0; nd < 8; nd++) {
                const uint32_t b0 = *(const uint32_t*)&Vt[nd * 8 + g][kk];
                const uint32_t b1 = *(const uint32_t*)&Vt[nd * 8 + g][kk + 8];
                mma_f16(o[nd], pa, b0, b1);
            }
        }
        __syncthreads();
    }

    const float i0 = 1.0f / l0, i1 = 1.0f / l1;
    __half* o0 = Og + (size_t)n * S * DM + h * HD + (size_t)(q0 + g) * DM;
    __half* o1 = o0 + (size_t)8 * DM;
    #pragma unroll
    for (int nd = 0; nd < 8; nd++) {
        const int col = nd * 8 + 2 * q4;
        *(uint32_t*)(o0 + col) = packh2(o[nd][0] * i0, o[nd][1] * i0);
        *(uint32_t*)(o1 + col) = packh2(o[nd][2] * i1, o[nd][3] * i1);
    }
}

// ---------------------------------------------------------------------------
// Transposes fp32 [rows][cols] -> fp16 [cols][rows]
// ---------------------------------------------------------------------------
__global__ __launch_bounds__(256) void transpose_h(
    const float* __restrict__ in, int rows, int cols, __half* __restrict__ out)
{
    __shared__ float t[32][33];
    const int c0 = blockIdx.x * 32, r0 = blockIdx.y * 32;
    const int tx = threadIdx.x & 31, ty = threadIdx.x >> 5;
    #pragma unroll
    for (int i = 0; i < 32; i += 8)
        t[ty + i][tx] = in[(size_t)(r0 + ty + i) * cols + c0 + tx];
    __syncthreads();
    #pragma unroll
    for (int i = 0; i < 32; i += 8)
        out[(size_t)(c0 + ty + i) * rows + r0 + tx] = __float2half(t[tx][ty + i]);
}

// 4 DM x DM weight transposes batched in one launch (z selects the matrix).
__global__ __launch_bounds__(256) void transpose_h4(
    const float* __restrict__ s0, const float* __restrict__ s1,
    const float* __restrict__ s2, const float* __restrict__ s3,
    __half* __restrict__ d0, __half* __restrict__ d1,
    __half* __restrict__ d2, __half* __restrict__ d3)
{
    __shared__ float t[32][33];
    const float* in;
    __half* out;
    switch (blockIdx.z) {
        case 0: in = s0; out = d0; break;
        case 1: in = s1; out = d1; break;
        case 2: in = s2; out = d2; break;
        default: in = s3; out = d3; break;
    }
    const int c0 = blockIdx.x * 32, r0 = blockIdx.y * 32;
    const int tx = threadIdx.x & 31, ty = threadIdx.x >> 5;
    #pragma unroll
    for (int i = 0; i < 32; i += 8)
        t[ty + i][tx] = in[(size_t)(r0 + ty + i) * DM + c0 + tx];
    __syncthreads();
    #pragma unroll
    for (int i = 0; i < 32; i += 8)
        out[(size_t)(c0 + ty + i) * DM + r0 + tx] = __float2half(t[tx][ty + i]);
}

// ---------------------------------------------------------------------------
// LayerNorm fp32 in -> fp16 out.
// ---------------------------------------------------------------------------
__global__ __launch_bounds__(256) void ln_h(
    const float* __restrict__ x, const float* __restrict__ g,
    const float* __restrict__ b, __half* __restrict__ y)
{
    const int row = blockIdx.x, t = threadIdx.x;
    float4 v = ((const float4*)(x + (size_t)row * DM))[t];
    float sum = v.x + v.y + v.z + v.w;
    float sq  = v.x*v.x + v.y*v.y + v.z*v.z + v.w*v.w;
    __shared__ float s1[256], s2[256];
    s1[t] = sum; s2[t] = sq;
    __syncthreads();
    #pragma unroll
    for (int st = 128; st > 0; st >>= 1) {
        if (t < st) { s1[t] += s1[t + st]; s2[t] += s2[t + st]; }
        __syncthreads();
    }
    const float mu  = s1[0] * (1.0f / DM);
    const float var = s2[0] * (1.0f / DM) - mu * mu;
    const float inv = rsqrtf(var + LN_EPS);
    const float4 gv = ((const float4*)g)[t];
    const float4 bv = ((const float4*)b)[t];
    uint2 ov;
    ov.x = packh2((v.x - mu) * inv * gv.x + bv.x, (v.y - mu) * inv * gv.y + bv.y);
    ov.y = packh2((v.z - mu) * inv * gv.z + bv.z, (v.w - mu) * inv * gv.w + bv.w);
    ((uint2*)(y + (size_t)row * DM))[t] = ov;
}

// ---------------------------------------------------------------------------
// Launch
// ---------------------------------------------------------------------------
extern "C" void kernel_launch(void* const* d_in, const int* in_sizes, int n_in,
                              void* d_out, int out_size)
{
    const float* x    = (const float*)d_in[0];
    const float* w_q  = (const float*)d_in[2];
    const float* w_k  = (const float*)d_in[3];
    const float* w_v  = (const float*)d_in[4];
    const float* w_0  = (const float*)d_in[5];
    const float* b_0  = (const float*)d_in[6];
    const float* w_1  = (const float*)d_in[7];
    const float* b_1  = (const float*)d_in[8];
    const float* w_2  = (const float*)d_in[9];
    const float* b_2  = (const float*)d_in[10];
    const float* g_1  = (const float*)d_in[11];
    const float* be_1 = (const float*)d_in[12];
    const float* g_2  = (const float*)d_in[13];
    const float* be_2 = (const float*)d_in[14];
    float* out = (float*)d_out;

    __half *xnh, *qkv, *aoh, *ffh, *wqkvt, *w0t, *w1t, *w2t;
    float* x2;
    cudaGetSymbolAddress((void**)&xnh, g_xnh);
    cudaGetSymbolAddress((void**)&qkv, g_qkv);
    cudaGetSymbolAddress((void**)&aoh, g_aoh);
    cudaGetSymbolAddress((void**)&ffh, g_ffh);
    cudaGetSymbolAddress((void**)&x2,  g_x2);
    cudaGetSymbolAddress((void**)&wqkvt, g_wqkvt);
    cudaGetSymbolAddress((void**)&w0t, g_w0t);
    cudaGetSymbolAddress((void**)&w1t, g_w1t);
    cudaGetSymbolAddress((void**)&w2t, g_w2t);

    const int DSMEM   = 3 * 128 * 40 * 2 * 2;              // 61440
    const int DSMEM256 = 3 * (256 + 128) * 40 * 2;         // 92160
    static bool attr_done = false;
    if (!attr_done) {
        cudaFuncSetAttribute(hgemm256<false,false>,
                             cudaFuncAttributeMaxDynamicSharedMemorySize, DSMEM256);
        cudaFuncSetAttribute(hgemm256<true,true>,
                             cudaFuncAttributeMaxDynamicSharedMemorySize, DSMEM256);
        cudaFuncSetAttribute(hgemm<true,false,true,false>,
                             cudaFuncAttributeMaxDynamicSharedMemorySize, DSMEM);
        attr_done = true;
    }

    // Weight transpose+convert: W[K][N] fp32 -> Wt[N][K] fp16 (QKV packed)
    transpose_h4<<<dim3(DM/32, DM/32, 4), 256>>>(
        w_q, w_k, w_v, w_0,
        wqkvt, wqkvt + (size_t)DM * DM, wqkvt + (size_t)2 * DM * DM, w0t);
    transpose_h<<<dim3(DFF/32, DM/32),  256>>>(w_1, DM, DFF, w1t);
    transpose_h<<<dim3(DM/32,  DFF/32), 256>>>(w_2, DFF, DM, w2t);

    // LN1 -> fp16
    ln_h<<<TOK, 256>>>(x, g_1, be_1, xnh);

    // Fused QKV projection: [4096, 3072] = xnh @ Wqkv^T  (256-row tiles)
    hgemm256<false,false><<<dim3(24, 16), 256, DSMEM256>>>(
        xnh, DM, wqkvt, DM, qkv, 3 * DM, nullptr, DM);

    // Fused attention
    flash_attn<<<dim3(S/128, NH, NB), 256>>>(qkv, aoh);

    // x2 = x + ao @ W0 + b0   (fp32 out)
    hgemm<true,false,true,false><<<dim3(8, 32), 256, DSMEM>>>(
        aoh, DM, w0t, DM, x2, DM, b_0, x, DM);

    // LN2 -> fp16
    ln_h<<<TOK, 256>>>(x2, g_2, be_2, xnh);

    // ff = relu(xn @ W1 + b1)  (fp16 out, 256-row tiles)
    hgemm256<true,true><<<dim3(32, 16), 256, DSMEM256>>>(
        xnh, DM, w1t, DM, ffh, DFF, b_1, DM);

    // out = x2 + ff @ W2 + b2  (fp32 out)
    hgemm<true,false,true,false><<<dim3(8, 32), 256, DSMEM>>>(
        ffh, DFF, w2t, DFF, out, DM, b_2, x2, DFF);
}